// round 13
// baseline (speedup 1.0000x reference)
#include <cuda_runtime.h>

// GlobalFilter: y = irfft2(rfft2(x, ortho) * W, ortho), 14x14 spatial, B=256, C=512.
// R13: R12/R6 base + 1/196 normalization folded OUT of stage B (weights used
//      raw: saves 28 muls/thread on the critical path) and INTO stage A''s
//      compile-time twiddle constants (free) + one f2mul per base term.

#define NC 32
#define NTHR 256

typedef unsigned long long u64;

__device__ __forceinline__ u64 pk2(float x, float y) {
    u64 r; asm("mov.b64 %0, {%1, %2};" : "=l"(r) : "f"(x), "f"(y)); return r;
}
__device__ __forceinline__ void upk2(u64 v, float& x, float& y) {
    asm("mov.b64 {%0, %1}, %2;" : "=f"(x), "=f"(y) : "l"(v));
}
__device__ __forceinline__ u64 f2fma(u64 a, u64 b, u64 c) {
    u64 d; asm("fma.rn.f32x2 %0, %1, %2, %3;" : "=l"(d) : "l"(a), "l"(b), "l"(c)); return d;
}
__device__ __forceinline__ u64 f2add(u64 a, u64 b) {
    u64 d; asm("add.rn.f32x2 %0, %1, %2;" : "=l"(d) : "l"(a), "l"(b)); return d;
}
__device__ __forceinline__ u64 f2sub(u64 a, u64 b) {
    u64 d; asm("sub.rn.f32x2 %0, %1, %2;" : "=l"(d) : "l"(a), "l"(b)); return d;
}
__device__ __forceinline__ u64 f2mul(u64 a, u64 b) {
    u64 d; asm("mul.rn.f32x2 %0, %1, %2;" : "=l"(d) : "l"(a), "l"(b)); return d;
}

__global__ __launch_bounds__(NTHR, 4) void gf_kernel(const float* __restrict__ x,
                                                     const float* __restrict__ w,
                                                     float* __restrict__ y) {
    __shared__ u64 E[14 * 8 * NC];   // interleaved complex (re, im) per channel, 28672 B

    const int b  = blockIdx.y;
    const int c0 = blockIdx.x * NC;
    const int tid = threadIdx.x;

    const float CC[14] = {
         1.0000000000000000f,  0.9009688679024191f,  0.6234898018587336f,
         0.2225209339563144f, -0.2225209339563143f, -0.6234898018587335f,
        -0.9009688679024191f, -1.0000000000000000f, -0.9009688679024191f,
        -0.6234898018587336f, -0.2225209339563146f,  0.2225209339563143f,
         0.6234898018587334f,  0.9009688679024190f
    };
    const float SS[14] = {
         0.0000000000000000f,  0.4338837391175581f,  0.7818314824680298f,
         0.9749279121818236f,  0.9749279121818236f,  0.7818314824680299f,
         0.4338837391175582f,  0.0000000000000000f, -0.4338837391175581f,
        -0.7818314824680297f, -0.9749279121818236f, -0.9749279121818238f,
        -0.7818314824680300f, -0.4338837391175583f
    };

    // ---- Stage A: rfft along q. 224 pair-tasks (2 channels each). ----
    if (tid < 224) {
        const int cp = (tid & 15) << 1;      // even channel within tile
        const int p  = tid >> 4;             // 0..13
        const float2* xp = reinterpret_cast<const float2*>(
            x + ((b * 196) + p * 14) * 512 + c0 + cp);

        u64 r[14];                           // lanes = (c0, c1)
        #pragma unroll
        for (int q = 0; q < 14; q++) {
            float2 t = xp[q * 256];
            r[q] = pk2(t.x, t.y);
        }
        u64 s[7], dd[7];
        #pragma unroll
        for (int j = 1; j <= 6; j++) {
            s[j]  = f2add(r[j], r[14 - j]);
            dd[j] = f2sub(r[j], r[14 - j]);
        }
        const u64 bs = f2add(r[0], r[7]);
        const u64 bd = f2sub(r[0], r[7]);
        {
            u64 e0 = bs, e7 = bd;
            #pragma unroll
            for (int j = 1; j <= 6; j++) {
                e0 = f2add(e0, s[j]);
                e7 = (j & 1) ? f2sub(e7, s[j]) : f2add(e7, s[j]);
            }
            float a0, a1, b0, b1;
            upk2(e0, a0, a1); upk2(e7, b0, b1);
            reinterpret_cast<float4*>(E + (p * 8 + 0) * NC + cp)[0] =
                make_float4(a0, 0.0f, a1, 0.0f);
            reinterpret_cast<float4*>(E + (p * 8 + 7) * NC + cp)[0] =
                make_float4(b0, 0.0f, b1, 0.0f);
        }
        #pragma unroll
        for (int k2 = 1; k2 <= 6; k2++) {
            u64 er = (k2 & 1) ? bd : bs;
            u64 ei = pk2(0.0f, 0.0f);
            #pragma unroll
            for (int j = 1; j <= 6; j++) {
                const int m = (k2 * j) % 14;
                er = f2fma(s[j],  pk2(CC[m], CC[m]), er);
                ei = f2fma(dd[j], pk2(-SS[m], -SS[m]), ei);
            }
            float er0, er1, ei0, ei1;
            upk2(er, er0, er1); upk2(ei, ei0, ei1);
            reinterpret_cast<float4*>(E + (p * 8 + k2) * NC + cp)[0] =
                make_float4(er0, ei0, er1, ei1);
        }
    }
    __syncthreads();

    // ---- Stage B: fft over p, * W (raw; 1/196 folded into stage A'),
    //      ifft over p. 1 task/thread. ----
    {
        const int c  = tid & (NC - 1);
        const int k2 = tid >> 5;
        u64* col = E + k2 * NC + c;          // element (p) at col[p * 8*NC]
        const int PS = 8 * NC;               // 256

        const u64 e0 = col[0];
        const u64 e7 = col[7 * PS];
        u64 s[7], d[7];
        #pragma unroll
        for (int j = 1; j <= 6; j++) {
            u64 a = col[j * PS], bb = col[(14 - j) * PS];
            s[j] = f2add(a, bb);
            d[j] = f2sub(a, bb);
        }

        const float2* wp = reinterpret_cast<const float2*>(w) + k2 * 512 + c0 + c;

        u64 z[14];
        const u64 bp = f2add(e0, e7);
        const u64 bm = f2sub(e0, e7);
        {
            const float2 wv0 = wp[0];
            const float2 wv7 = wp[7 * 8 * 512];
            u64 z0 = bp, z7 = bm;
            #pragma unroll
            for (int j = 1; j <= 6; j++) {
                z0 = f2add(z0, s[j]);
                z7 = (j & 1) ? f2sub(z7, s[j]) : f2add(z7, s[j]);
            }
            float zr, zi;
            upk2(z0, zr, zi);
            z[0] = pk2(zr * wv0.x - zi * wv0.y, zr * wv0.y + zi * wv0.x);
            upk2(z7, zr, zi);
            z[7] = pk2(zr * wv7.x - zi * wv7.y, zr * wv7.y + zi * wv7.x);
        }
        #pragma unroll
        for (int k1 = 1; k1 <= 6; k1++) {
            const float2 wvA = wp[k1 * 8 * 512];
            const float2 wvB = wp[(14 - k1) * 8 * 512];
            u64 AC = f2mul(s[1], pk2(CC[k1 % 14], CC[k1 % 14]));
            u64 DB = f2mul(d[1], pk2(SS[k1 % 14], SS[k1 % 14]));
            #pragma unroll
            for (int j = 2; j <= 6; j++) {
                const int m = (k1 * j) % 14;
                AC = f2fma(s[j], pk2(CC[m], CC[m]), AC);
                DB = f2fma(d[j], pk2(SS[m], SS[m]), DB);
            }
            float A, C, D, Bv, bR, bI;
            upk2(AC, A, C); upk2(DB, D, Bv);
            upk2((k1 & 1) ? bm : bp, bR, bI);
            const float zra = bR + A + Bv, zia = bI + C - D;
            const float zrb = bR + A - Bv, zib = bI + C + D;
            z[k1]      = pk2(zra * wvA.x - zia * wvA.y, zra * wvA.y + zia * wvA.x);
            z[14 - k1] = pk2(zrb * wvB.x - zib * wvB.y, zrb * wvB.y + zib * wvB.x);
        }

        const u64 zp = f2add(z[0], z[7]);
        const u64 zm = f2sub(z[0], z[7]);
        u64 s2[7], d2[7];
        #pragma unroll
        for (int j = 1; j <= 6; j++) {
            s2[j] = f2add(z[j], z[14 - j]);
            d2[j] = f2sub(z[j], z[14 - j]);
        }
        {
            u64 o0 = zp, o7 = zm;
            #pragma unroll
            for (int j = 1; j <= 6; j++) {
                o0 = f2add(o0, s2[j]);
                o7 = (j & 1) ? f2sub(o7, s2[j]) : f2add(o7, s2[j]);
            }
            col[0]      = o0;
            col[7 * PS] = o7;
        }
        #pragma unroll
        for (int p = 1; p <= 6; p++) {
            u64 AC = f2mul(s2[1], pk2(CC[p % 14], CC[p % 14]));
            u64 DB = f2mul(d2[1], pk2(SS[p % 14], SS[p % 14]));
            #pragma unroll
            for (int j = 2; j <= 6; j++) {
                const int m = (p * j) % 14;
                AC = f2fma(s2[j], pk2(CC[m], CC[m]), AC);
                DB = f2fma(d2[j], pk2(SS[m], SS[m]), DB);
            }
            float A, C, D, Bv, bR, bI;
            upk2(AC, A, C); upk2(DB, D, Bv);
            upk2((p & 1) ? zm : zp, bR, bI);
            col[p * PS]        = pk2(bR + A - Bv, bI + C + D);
            col[(14 - p) * PS] = pk2(bR + A + Bv, bI + C - D);
        }
    }
    __syncthreads();

    // ---- Stage A': irfft along q with 1/196 folded into constants.
    //      224 pair-tasks (2 channels each). ----
    if (tid < 224) {
        const int cp = (tid & 15) << 1;
        const int p  = tid >> 4;
        const float4* row = reinterpret_cast<const float4*>(E + (p * 8) * NC + cp);

        const float inv196 = 1.0f / 196.0f;
        const float n2 = 2.0f / 196.0f;      // compile-time constant

        u64 ea[8], eb[8];
        u64 rr[8];
        #pragma unroll
        for (int k2 = 0; k2 < 8; k2++) {
            float4 t = row[k2 * (NC / 2)];
            ea[k2] = pk2(t.x, t.y);
            eb[k2] = pk2(t.z, t.w);
            rr[k2] = pk2(t.x, t.z);
        }

        float2* yout = reinterpret_cast<float2*>(
            y + ((b * 196) + p * 14) * 512 + c0 + cp);

        const u64 nrm   = pk2(inv196, inv196);
        const u64 base_e = f2mul(f2add(rr[0], rr[7]), nrm);   // scaled bases
        const u64 base_o = f2mul(f2sub(rr[0], rr[7]), nrm);
        {
            u64 v0 = base_e, v7 = base_o;
            const u64 two_ = pk2(n2, n2);
            const u64 ntwo = pk2(-n2, -n2);
            #pragma unroll
            for (int k2 = 1; k2 <= 6; k2++) {
                v0 = f2fma(rr[k2], two_, v0);
                v7 = f2fma(rr[k2], (k2 & 1) ? ntwo : two_, v7);
            }
            float v00, v01, v70, v71;
            upk2(v0, v00, v01); upk2(v7, v70, v71);
            yout[0]       = make_float2(v00, v01);
            yout[7 * 256] = make_float2(v70, v71);
        }
        #pragma unroll
        for (int q = 1; q <= 6; q++) {
            u64 AB0 = f2mul(ea[1], pk2(n2 * CC[q % 14], n2 * SS[q % 14]));
            u64 AB1 = f2mul(eb[1], pk2(n2 * CC[q % 14], n2 * SS[q % 14]));
            #pragma unroll
            for (int k2 = 2; k2 <= 6; k2++) {
                const int m = (k2 * q) % 14;
                const u64 tw = pk2(n2 * CC[m], n2 * SS[m]);
                AB0 = f2fma(ea[k2], tw, AB0);
                AB1 = f2fma(eb[k2], tw, AB1);
            }
            float A0, B0, A1, B1, bc0, bc1;
            upk2(AB0, A0, B0); upk2(AB1, A1, B1);
            upk2((q & 1) ? base_o : base_e, bc0, bc1);
            yout[q * 256]        = make_float2(bc0 + A0 - B0, bc1 + A1 - B1);
            yout[(14 - q) * 256] = make_float2(bc0 + A0 + B0, bc1 + A1 + B1);
        }
    }
}

extern "C" void kernel_launch(void* const* d_in, const int* in_sizes, int n_in,
                              void* d_out, int out_size) {
    const float* x = (const float*)d_in[0];        // [256,196,512] f32
    const float* w = (const float*)d_in[1];        // [14,8,512,2]  f32
    float* y = (float*)d_out;                      // [256,196,512] f32

    dim3 grid(512 / NC, 256);                      // 16 x 256 = 4096 CTAs
    gf_kernel<<<grid, NTHR>>>(x, w, y);
}

// round 14
// speedup vs baseline: 1.0052x; 1.0052x over previous
#include <cuda_runtime.h>

// GlobalFilter: y = irfft2(rfft2(x, ortho) * W, ortho), 14x14 spatial, B=256, C=512.
// R14 (converged): R13 body + dependency-chain trims (stage-A ei chains start
//   with f2mul; stage-B reuses bp/bm for DC/Nyquist). Structure:
//   - Stages A/A': 2 adjacent channels per thread (channel-lane f32x2),
//     LDG.64/STG.64 global + LDS.128/STS.128 shared, 224 single tasks.
//   - Stage B: per-(k2,c) complex-lane f32x2, folded + output-paired 14-pt
//     DFTs, raw-weight multiply fused in pair loop; 1/196 folded into the
//     compile-time twiddles of stage A'.

#define NC 32
#define NTHR 256

typedef unsigned long long u64;

__device__ __forceinline__ u64 pk2(float x, float y) {
    u64 r; asm("mov.b64 %0, {%1, %2};" : "=l"(r) : "f"(x), "f"(y)); return r;
}
__device__ __forceinline__ void upk2(u64 v, float& x, float& y) {
    asm("mov.b64 {%0, %1}, %2;" : "=f"(x), "=f"(y) : "l"(v));
}
__device__ __forceinline__ u64 f2fma(u64 a, u64 b, u64 c) {
    u64 d; asm("fma.rn.f32x2 %0, %1, %2, %3;" : "=l"(d) : "l"(a), "l"(b), "l"(c)); return d;
}
__device__ __forceinline__ u64 f2add(u64 a, u64 b) {
    u64 d; asm("add.rn.f32x2 %0, %1, %2;" : "=l"(d) : "l"(a), "l"(b)); return d;
}
__device__ __forceinline__ u64 f2sub(u64 a, u64 b) {
    u64 d; asm("sub.rn.f32x2 %0, %1, %2;" : "=l"(d) : "l"(a), "l"(b)); return d;
}
__device__ __forceinline__ u64 f2mul(u64 a, u64 b) {
    u64 d; asm("mul.rn.f32x2 %0, %1, %2;" : "=l"(d) : "l"(a), "l"(b)); return d;
}

__global__ __launch_bounds__(NTHR, 4) void gf_kernel(const float* __restrict__ x,
                                                     const float* __restrict__ w,
                                                     float* __restrict__ y) {
    __shared__ u64 E[14 * 8 * NC];   // interleaved complex (re, im) per channel, 28672 B

    const int b  = blockIdx.y;
    const int c0 = blockIdx.x * NC;
    const int tid = threadIdx.x;

    const float CC[14] = {
         1.0000000000000000f,  0.9009688679024191f,  0.6234898018587336f,
         0.2225209339563144f, -0.2225209339563143f, -0.6234898018587335f,
        -0.9009688679024191f, -1.0000000000000000f, -0.9009688679024191f,
        -0.6234898018587336f, -0.2225209339563146f,  0.2225209339563143f,
         0.6234898018587334f,  0.9009688679024190f
    };
    const float SS[14] = {
         0.0000000000000000f,  0.4338837391175581f,  0.7818314824680298f,
         0.9749279121818236f,  0.9749279121818236f,  0.7818314824680299f,
         0.4338837391175582f,  0.0000000000000000f, -0.4338837391175581f,
        -0.7818314824680297f, -0.9749279121818236f, -0.9749279121818238f,
        -0.7818314824680300f, -0.4338837391175583f
    };

    // ---- Stage A: rfft along q. 224 pair-tasks (2 channels each). ----
    if (tid < 224) {
        const int cp = (tid & 15) << 1;      // even channel within tile
        const int p  = tid >> 4;             // 0..13
        const float2* xp = reinterpret_cast<const float2*>(
            x + ((b * 196) + p * 14) * 512 + c0 + cp);

        u64 r[14];                           // lanes = (c0, c1)
        #pragma unroll
        for (int q = 0; q < 14; q++) {
            float2 t = xp[q * 256];
            r[q] = pk2(t.x, t.y);
        }
        u64 s[7], dd[7];
        #pragma unroll
        for (int j = 1; j <= 6; j++) {
            s[j]  = f2add(r[j], r[14 - j]);
            dd[j] = f2sub(r[j], r[14 - j]);
        }
        const u64 bs = f2add(r[0], r[7]);
        const u64 bd = f2sub(r[0], r[7]);
        {
            u64 e0 = bs, e7 = bd;
            #pragma unroll
            for (int j = 1; j <= 6; j++) {
                e0 = f2add(e0, s[j]);
                e7 = (j & 1) ? f2sub(e7, s[j]) : f2add(e7, s[j]);
            }
            float a0, a1, b0, b1;
            upk2(e0, a0, a1); upk2(e7, b0, b1);
            reinterpret_cast<float4*>(E + (p * 8 + 0) * NC + cp)[0] =
                make_float4(a0, 0.0f, a1, 0.0f);
            reinterpret_cast<float4*>(E + (p * 8 + 7) * NC + cp)[0] =
                make_float4(b0, 0.0f, b1, 0.0f);
        }
        #pragma unroll
        for (int k2 = 1; k2 <= 6; k2++) {
            u64 er = (k2 & 1) ? bd : bs;
            // ei chain starts with a mul (depth 6, not 7)
            u64 ei = f2mul(dd[1], pk2(-SS[k2 % 14], -SS[k2 % 14]));
            er = f2fma(s[1], pk2(CC[k2 % 14], CC[k2 % 14]), er);
            #pragma unroll
            for (int j = 2; j <= 6; j++) {
                const int m = (k2 * j) % 14;
                er = f2fma(s[j],  pk2(CC[m], CC[m]), er);
                ei = f2fma(dd[j], pk2(-SS[m], -SS[m]), ei);
            }
            float er0, er1, ei0, ei1;
            upk2(er, er0, er1); upk2(ei, ei0, ei1);
            reinterpret_cast<float4*>(E + (p * 8 + k2) * NC + cp)[0] =
                make_float4(er0, ei0, er1, ei1);
        }
    }
    __syncthreads();

    // ---- Stage B: fft over p, * W (raw), ifft over p. 1 task/thread. ----
    {
        const int c  = tid & (NC - 1);
        const int k2 = tid >> 5;
        u64* col = E + k2 * NC + c;          // element (p) at col[p * 8*NC]
        const int PS = 8 * NC;               // 256

        const u64 e0 = col[0];
        const u64 e7 = col[7 * PS];
        u64 s[7], d[7];
        #pragma unroll
        for (int j = 1; j <= 6; j++) {
            u64 a = col[j * PS], bb = col[(14 - j) * PS];
            s[j] = f2add(a, bb);
            d[j] = f2sub(a, bb);
        }

        const float2* wp = reinterpret_cast<const float2*>(w) + k2 * 512 + c0 + c;

        u64 z[14];
        const u64 bp = f2add(e0, e7);
        const u64 bm = f2sub(e0, e7);
        {
            const float2 wv0 = wp[0];
            const float2 wv7 = wp[7 * 8 * 512];
            u64 z0 = bp, z7 = bm;            // reuse bp/bm (no recompute)
            #pragma unroll
            for (int j = 1; j <= 6; j++) {
                z0 = f2add(z0, s[j]);
                z7 = (j & 1) ? f2sub(z7, s[j]) : f2add(z7, s[j]);
            }
            float zr, zi;
            upk2(z0, zr, zi);
            z[0] = pk2(zr * wv0.x - zi * wv0.y, zr * wv0.y + zi * wv0.x);
            upk2(z7, zr, zi);
            z[7] = pk2(zr * wv7.x - zi * wv7.y, zr * wv7.y + zi * wv7.x);
        }
        #pragma unroll
        for (int k1 = 1; k1 <= 6; k1++) {
            const float2 wvA = wp[k1 * 8 * 512];
            const float2 wvB = wp[(14 - k1) * 8 * 512];
            u64 AC = f2mul(s[1], pk2(CC[k1 % 14], CC[k1 % 14]));
            u64 DB = f2mul(d[1], pk2(SS[k1 % 14], SS[k1 % 14]));
            #pragma unroll
            for (int j = 2; j <= 6; j++) {
                const int m = (k1 * j) % 14;
                AC = f2fma(s[j], pk2(CC[m], CC[m]), AC);
                DB = f2fma(d[j], pk2(SS[m], SS[m]), DB);
            }
            float A, C, D, Bv, bR, bI;
            upk2(AC, A, C); upk2(DB, D, Bv);
            upk2((k1 & 1) ? bm : bp, bR, bI);
            const float zra = bR + A + Bv, zia = bI + C - D;
            const float zrb = bR + A - Bv, zib = bI + C + D;
            z[k1]      = pk2(zra * wvA.x - zia * wvA.y, zra * wvA.y + zia * wvA.x);
            z[14 - k1] = pk2(zrb * wvB.x - zib * wvB.y, zrb * wvB.y + zib * wvB.x);
        }

        const u64 zp = f2add(z[0], z[7]);
        const u64 zm = f2sub(z[0], z[7]);
        u64 s2[7], d2[7];
        #pragma unroll
        for (int j = 1; j <= 6; j++) {
            s2[j] = f2add(z[j], z[14 - j]);
            d2[j] = f2sub(z[j], z[14 - j]);
        }
        {
            u64 o0 = zp, o7 = zm;
            #pragma unroll
            for (int j = 1; j <= 6; j++) {
                o0 = f2add(o0, s2[j]);
                o7 = (j & 1) ? f2sub(o7, s2[j]) : f2add(o7, s2[j]);
            }
            col[0]      = o0;
            col[7 * PS] = o7;
        }
        #pragma unroll
        for (int p = 1; p <= 6; p++) {
            u64 AC = f2mul(s2[1], pk2(CC[p % 14], CC[p % 14]));
            u64 DB = f2mul(d2[1], pk2(SS[p % 14], SS[p % 14]));
            #pragma unroll
            for (int j = 2; j <= 6; j++) {
                const int m = (p * j) % 14;
                AC = f2fma(s2[j], pk2(CC[m], CC[m]), AC);
                DB = f2fma(d2[j], pk2(SS[m], SS[m]), DB);
            }
            float A, C, D, Bv, bR, bI;
            upk2(AC, A, C); upk2(DB, D, Bv);
            upk2((p & 1) ? zm : zp, bR, bI);
            col[p * PS]        = pk2(bR + A - Bv, bI + C + D);
            col[(14 - p) * PS] = pk2(bR + A + Bv, bI + C - D);
        }
    }
    __syncthreads();

    // ---- Stage A': irfft along q; 1/196 folded into constants.
    //      224 pair-tasks (2 channels each). ----
    if (tid < 224) {
        const int cp = (tid & 15) << 1;
        const int p  = tid >> 4;
        const float4* row = reinterpret_cast<const float4*>(E + (p * 8) * NC + cp);

        const float inv196 = 1.0f / 196.0f;
        const float n2 = 2.0f / 196.0f;

        u64 ea[8], eb[8];
        u64 rr[8];
        #pragma unroll
        for (int k2 = 0; k2 < 8; k2++) {
            float4 t = row[k2 * (NC / 2)];
            ea[k2] = pk2(t.x, t.y);
            eb[k2] = pk2(t.z, t.w);
            rr[k2] = pk2(t.x, t.z);
        }

        float2* yout = reinterpret_cast<float2*>(
            y + ((b * 196) + p * 14) * 512 + c0 + cp);

        const u64 nrm    = pk2(inv196, inv196);
        const u64 base_e = f2mul(f2add(rr[0], rr[7]), nrm);
        const u64 base_o = f2mul(f2sub(rr[0], rr[7]), nrm);
        {
            u64 v0 = base_e, v7 = base_o;
            const u64 two_ = pk2(n2, n2);
            const u64 ntwo = pk2(-n2, -n2);
            #pragma unroll
            for (int k2 = 1; k2 <= 6; k2++) {
                v0 = f2fma(rr[k2], two_, v0);
                v7 = f2fma(rr[k2], (k2 & 1) ? ntwo : two_, v7);
            }
            float v00, v01, v70, v71;
            upk2(v0, v00, v01); upk2(v7, v70, v71);
            yout[0]       = make_float2(v00, v01);
            yout[7 * 256] = make_float2(v70, v71);
        }
        #pragma unroll
        for (int q = 1; q <= 6; q++) {
            u64 AB0 = f2mul(ea[1], pk2(n2 * CC[q % 14], n2 * SS[q % 14]));
            u64 AB1 = f2mul(eb[1], pk2(n2 * CC[q % 14], n2 * SS[q % 14]));
            #pragma unroll
            for (int k2 = 2; k2 <= 6; k2++) {
                const int m = (k2 * q) % 14;
                const u64 tw = pk2(n2 * CC[m], n2 * SS[m]);
                AB0 = f2fma(ea[k2], tw, AB0);
                AB1 = f2fma(eb[k2], tw, AB1);
            }
            float A0, B0, A1, B1, bc0, bc1;
            upk2(AB0, A0, B0); upk2(AB1, A1, B1);
            upk2((q & 1) ? base_o : base_e, bc0, bc1);
            yout[q * 256]        = make_float2(bc0 + A0 - B0, bc1 + A1 - B1);
            yout[(14 - q) * 256] = make_float2(bc0 + A0 + B0, bc1 + A1 + B1);
        }
    }
}

extern "C" void kernel_launch(void* const* d_in, const int* in_sizes, int n_in,
                              void* d_out, int out_size) {
    const float* x = (const float*)d_in[0];        // [256,196,512] f32
    const float* w = (const float*)d_in[1];        // [14,8,512,2]  f32
    float* y = (float*)d_out;                      // [256,196,512] f32

    dim3 grid(512 / NC, 256);                      // 16 x 256 = 4096 CTAs
    gf_kernel<<<grid, NTHR>>>(x, w, y);
}

// round 15
// speedup vs baseline: 1.0394x; 1.0340x over previous
#include <cuda_runtime.h>

// GlobalFilter: y = irfft2(rfft2(x, ortho) * W, ortho), 14x14 spatial, B=256, C=512.
// R15: R14 + stage-B z-array fold (s2/d2 formed inside the k1 pair loop; z[14]
//      never materializes) at launch_bounds(256,4) — isolating the fold from
//      R9's occupancy-5 confound. Everything else identical to R14.

#define NC 32
#define NTHR 256

typedef unsigned long long u64;

__device__ __forceinline__ u64 pk2(float x, float y) {
    u64 r; asm("mov.b64 %0, {%1, %2};" : "=l"(r) : "f"(x), "f"(y)); return r;
}
__device__ __forceinline__ void upk2(u64 v, float& x, float& y) {
    asm("mov.b64 {%0, %1}, %2;" : "=f"(x), "=f"(y) : "l"(v));
}
__device__ __forceinline__ u64 f2fma(u64 a, u64 b, u64 c) {
    u64 d; asm("fma.rn.f32x2 %0, %1, %2, %3;" : "=l"(d) : "l"(a), "l"(b), "l"(c)); return d;
}
__device__ __forceinline__ u64 f2add(u64 a, u64 b) {
    u64 d; asm("add.rn.f32x2 %0, %1, %2;" : "=l"(d) : "l"(a), "l"(b)); return d;
}
__device__ __forceinline__ u64 f2sub(u64 a, u64 b) {
    u64 d; asm("sub.rn.f32x2 %0, %1, %2;" : "=l"(d) : "l"(a), "l"(b)); return d;
}
__device__ __forceinline__ u64 f2mul(u64 a, u64 b) {
    u64 d; asm("mul.rn.f32x2 %0, %1, %2;" : "=l"(d) : "l"(a), "l"(b)); return d;
}

__global__ __launch_bounds__(NTHR, 4) void gf_kernel(const float* __restrict__ x,
                                                     const float* __restrict__ w,
                                                     float* __restrict__ y) {
    __shared__ u64 E[14 * 8 * NC];   // interleaved complex (re, im) per channel, 28672 B

    const int b  = blockIdx.y;
    const int c0 = blockIdx.x * NC;
    const int tid = threadIdx.x;

    const float CC[14] = {
         1.0000000000000000f,  0.9009688679024191f,  0.6234898018587336f,
         0.2225209339563144f, -0.2225209339563143f, -0.6234898018587335f,
        -0.9009688679024191f, -1.0000000000000000f, -0.9009688679024191f,
        -0.6234898018587336f, -0.2225209339563146f,  0.2225209339563143f,
         0.6234898018587334f,  0.9009688679024190f
    };
    const float SS[14] = {
         0.0000000000000000f,  0.4338837391175581f,  0.7818314824680298f,
         0.9749279121818236f,  0.9749279121818236f,  0.7818314824680299f,
         0.4338837391175582f,  0.0000000000000000f, -0.4338837391175581f,
        -0.7818314824680297f, -0.9749279121818236f, -0.9749279121818238f,
        -0.7818314824680300f, -0.4338837391175583f
    };

    // ---- Stage A: rfft along q. 224 pair-tasks (2 channels each). ----
    if (tid < 224) {
        const int cp = (tid & 15) << 1;      // even channel within tile
        const int p  = tid >> 4;             // 0..13
        const float2* xp = reinterpret_cast<const float2*>(
            x + ((b * 196) + p * 14) * 512 + c0 + cp);

        u64 r[14];                           // lanes = (c0, c1)
        #pragma unroll
        for (int q = 0; q < 14; q++) {
            float2 t = xp[q * 256];
            r[q] = pk2(t.x, t.y);
        }
        u64 s[7], dd[7];
        #pragma unroll
        for (int j = 1; j <= 6; j++) {
            s[j]  = f2add(r[j], r[14 - j]);
            dd[j] = f2sub(r[j], r[14 - j]);
        }
        const u64 bs = f2add(r[0], r[7]);
        const u64 bd = f2sub(r[0], r[7]);
        {
            u64 e0 = bs, e7 = bd;
            #pragma unroll
            for (int j = 1; j <= 6; j++) {
                e0 = f2add(e0, s[j]);
                e7 = (j & 1) ? f2sub(e7, s[j]) : f2add(e7, s[j]);
            }
            float a0, a1, b0, b1;
            upk2(e0, a0, a1); upk2(e7, b0, b1);
            reinterpret_cast<float4*>(E + (p * 8 + 0) * NC + cp)[0] =
                make_float4(a0, 0.0f, a1, 0.0f);
            reinterpret_cast<float4*>(E + (p * 8 + 7) * NC + cp)[0] =
                make_float4(b0, 0.0f, b1, 0.0f);
        }
        #pragma unroll
        for (int k2 = 1; k2 <= 6; k2++) {
            u64 er = (k2 & 1) ? bd : bs;
            u64 ei = f2mul(dd[1], pk2(-SS[k2 % 14], -SS[k2 % 14]));
            er = f2fma(s[1], pk2(CC[k2 % 14], CC[k2 % 14]), er);
            #pragma unroll
            for (int j = 2; j <= 6; j++) {
                const int m = (k2 * j) % 14;
                er = f2fma(s[j],  pk2(CC[m], CC[m]), er);
                ei = f2fma(dd[j], pk2(-SS[m], -SS[m]), ei);
            }
            float er0, er1, ei0, ei1;
            upk2(er, er0, er1); upk2(ei, ei0, ei1);
            reinterpret_cast<float4*>(E + (p * 8 + k2) * NC + cp)[0] =
                make_float4(er0, ei0, er1, ei1);
        }
    }
    __syncthreads();

    // ---- Stage B: fft over p, * W (raw), ifft over p; z folded to s2/d2
    //      inside the pair loop (no z[14] array). 1 task/thread. ----
    {
        const int c  = tid & (NC - 1);
        const int k2 = tid >> 5;
        u64* col = E + k2 * NC + c;          // element (p) at col[p * 8*NC]
        const int PS = 8 * NC;               // 256

        const u64 e0 = col[0];
        const u64 e7 = col[7 * PS];
        u64 s[7], d[7];
        #pragma unroll
        for (int j = 1; j <= 6; j++) {
            u64 a = col[j * PS], bb = col[(14 - j) * PS];
            s[j] = f2add(a, bb);
            d[j] = f2sub(a, bb);
        }

        const float2* wp = reinterpret_cast<const float2*>(w) + k2 * 512 + c0 + c;

        const u64 bp = f2add(e0, e7);
        const u64 bm = f2sub(e0, e7);

        u64 z0, z7;                          // weighted DC / Nyquist
        {
            const float2 wv0 = wp[0];
            const float2 wv7 = wp[7 * 8 * 512];
            u64 a0 = bp, a7 = bm;
            #pragma unroll
            for (int j = 1; j <= 6; j++) {
                a0 = f2add(a0, s[j]);
                a7 = (j & 1) ? f2sub(a7, s[j]) : f2add(a7, s[j]);
            }
            float zr, zi;
            upk2(a0, zr, zi);
            z0 = pk2(zr * wv0.x - zi * wv0.y, zr * wv0.y + zi * wv0.x);
            upk2(a7, zr, zi);
            z7 = pk2(zr * wv7.x - zi * wv7.y, zr * wv7.y + zi * wv7.x);
        }

        u64 s2[7], d2[7];                    // folded weighted pairs
        #pragma unroll
        for (int k1 = 1; k1 <= 6; k1++) {
            const float2 wvA = wp[k1 * 8 * 512];
            const float2 wvB = wp[(14 - k1) * 8 * 512];
            u64 AC = f2mul(s[1], pk2(CC[k1 % 14], CC[k1 % 14]));
            u64 DB = f2mul(d[1], pk2(SS[k1 % 14], SS[k1 % 14]));
            #pragma unroll
            for (int j = 2; j <= 6; j++) {
                const int m = (k1 * j) % 14;
                AC = f2fma(s[j], pk2(CC[m], CC[m]), AC);
                DB = f2fma(d[j], pk2(SS[m], SS[m]), DB);
            }
            float A, C, D, Bv, bR, bI;
            upk2(AC, A, C); upk2(DB, D, Bv);
            upk2((k1 & 1) ? bm : bp, bR, bI);
            const float zra = bR + A + Bv, zia = bI + C - D;     // Z[k1]
            const float zrb = bR + A - Bv, zib = bI + C + D;     // Z[14-k1]
            const float zAr = zra * wvA.x - zia * wvA.y, zAi = zra * wvA.y + zia * wvA.x;
            const float zBr = zrb * wvB.x - zib * wvB.y, zBi = zrb * wvB.y + zib * wvB.x;
            s2[k1] = pk2(zAr + zBr, zAi + zBi);   // z never stored
            d2[k1] = pk2(zAr - zBr, zAi - zBi);
        }

        // inverse fft over p (e^{+i theta}) from z0, z7, s2, d2
        const u64 zp = f2add(z0, z7);
        const u64 zm = f2sub(z0, z7);
        {
            u64 o0 = zp, o7 = zm;
            #pragma unroll
            for (int j = 1; j <= 6; j++) {
                o0 = f2add(o0, s2[j]);
                o7 = (j & 1) ? f2sub(o7, s2[j]) : f2add(o7, s2[j]);
            }
            col[0]      = o0;
            col[7 * PS] = o7;
        }
        #pragma unroll
        for (int p = 1; p <= 6; p++) {
            u64 AC = f2mul(s2[1], pk2(CC[p % 14], CC[p % 14]));
            u64 DB = f2mul(d2[1], pk2(SS[p % 14], SS[p % 14]));
            #pragma unroll
            for (int j = 2; j <= 6; j++) {
                const int m = (p * j) % 14;
                AC = f2fma(s2[j], pk2(CC[m], CC[m]), AC);
                DB = f2fma(d2[j], pk2(SS[m], SS[m]), DB);
            }
            float A, C, D, Bv, bR, bI;
            upk2(AC, A, C); upk2(DB, D, Bv);
            upk2((p & 1) ? zm : zp, bR, bI);
            col[p * PS]        = pk2(bR + A - Bv, bI + C + D);
            col[(14 - p) * PS] = pk2(bR + A + Bv, bI + C - D);
        }
    }
    __syncthreads();

    // ---- Stage A': irfft along q; 1/196 folded into constants.
    //      224 pair-tasks (2 channels each). ----
    if (tid < 224) {
        const int cp = (tid & 15) << 1;
        const int p  = tid >> 4;
        const float4* row = reinterpret_cast<const float4*>(E + (p * 8) * NC + cp);

        const float inv196 = 1.0f / 196.0f;
        const float n2 = 2.0f / 196.0f;

        u64 ea[8], eb[8];
        u64 rr[8];
        #pragma unroll
        for (int k2 = 0; k2 < 8; k2++) {
            float4 t = row[k2 * (NC / 2)];
            ea[k2] = pk2(t.x, t.y);
            eb[k2] = pk2(t.z, t.w);
            rr[k2] = pk2(t.x, t.z);
        }

        float2* yout = reinterpret_cast<float2*>(
            y + ((b * 196) + p * 14) * 512 + c0 + cp);

        const u64 nrm    = pk2(inv196, inv196);
        const u64 base_e = f2mul(f2add(rr[0], rr[7]), nrm);
        const u64 base_o = f2mul(f2sub(rr[0], rr[7]), nrm);
        {
            u64 v0 = base_e, v7 = base_o;
            const u64 two_ = pk2(n2, n2);
            const u64 ntwo = pk2(-n2, -n2);
            #pragma unroll
            for (int k2 = 1; k2 <= 6; k2++) {
                v0 = f2fma(rr[k2], two_, v0);
                v7 = f2fma(rr[k2], (k2 & 1) ? ntwo : two_, v7);
            }
            float v00, v01, v70, v71;
            upk2(v0, v00, v01); upk2(v7, v70, v71);
            yout[0]       = make_float2(v00, v01);
            yout[7 * 256] = make_float2(v70, v71);
        }
        #pragma unroll
        for (int q = 1; q <= 6; q++) {
            u64 AB0 = f2mul(ea[1], pk2(n2 * CC[q % 14], n2 * SS[q % 14]));
            u64 AB1 = f2mul(eb[1], pk2(n2 * CC[q % 14], n2 * SS[q % 14]));
            #pragma unroll
            for (int k2 = 2; k2 <= 6; k2++) {
                const int m = (k2 * q) % 14;
                const u64 tw = pk2(n2 * CC[m], n2 * SS[m]);
                AB0 = f2fma(ea[k2], tw, AB0);
                AB1 = f2fma(eb[k2], tw, AB1);
            }
            float A0, B0, A1, B1, bc0, bc1;
            upk2(AB0, A0, B0); upk2(AB1, A1, B1);
            upk2((q & 1) ? base_o : base_e, bc0, bc1);
            yout[q * 256]        = make_float2(bc0 + A0 - B0, bc1 + A1 - B1);
            yout[(14 - q) * 256] = make_float2(bc0 + A0 + B0, bc1 + A1 + B1);
        }
    }
}

extern "C" void kernel_launch(void* const* d_in, const int* in_sizes, int n_in,
                              void* d_out, int out_size) {
    const float* x = (const float*)d_in[0];        // [256,196,512] f32
    const float* w = (const float*)d_in[1];        // [14,8,512,2]  f32
    float* y = (float*)d_out;                      // [256,196,512] f32

    dim3 grid(512 / NC, 256);                      // 16 x 256 = 4096 CTAs
    gf_kernel<<<grid, NTHR>>>(x, w, y);
}